// round 11
// baseline (speedup 1.0000x reference)
#include <cuda_runtime.h>
#include <cstddef>
#include <cstdint>

// Problem constants
#define BATCH 32
#define NTOK  4900
#define DMODEL 256
#define HEADS 4
#define DH 64
#define WIN 49
#define RATE 5
#define NSEG 20
#define MROWS (BATCH*NTOK)   // 156800
#define GK 256

__device__ float g_q[(size_t)MROWS * DMODEL];     // proj1 out (tf32-rounded bits)
__device__ float g_att[(size_t)MROWS * DMODEL];   // attn out  (tf32-rounded bits)
__device__ uint32_t g_wq_t[GK * GK];              // Wq pre-rounded to tf32
__device__ uint32_t g_wo_t[GK * GK];              // Wo pre-rounded to tf32

__device__ __forceinline__ uint32_t to_tf32(float x) {
    uint32_t y;
    asm("cvt.rna.tf32.f32 %0, %1;" : "=r"(y) : "f"(x));
    return y;
}

__device__ __forceinline__ void mma_tf32_r(float* c,
                                           uint32_t a0, uint32_t a1, uint32_t a2, uint32_t a3,
                                           uint32_t b0, uint32_t b1) {
    asm volatile(
        "mma.sync.aligned.m16n8k8.row.col.f32.tf32.tf32.f32 "
        "{%0,%1,%2,%3}, {%4,%5,%6,%7}, {%8,%9}, {%0,%1,%2,%3};\n"
        : "+f"(c[0]), "+f"(c[1]), "+f"(c[2]), "+f"(c[3])
        : "r"(a0), "r"(a1), "r"(a2), "r"(a3), "r"(b0), "r"(b1));
}

// ---------------------------------------------------------------------------
// Prep: round both weight matrices to tf32 bits once.
// ---------------------------------------------------------------------------
__global__ void convert_w_kernel(const float* __restrict__ Wq,
                                 const float* __restrict__ Wo,
                                 uint32_t* __restrict__ wq,
                                 uint32_t* __restrict__ wo) {
    int i = blockIdx.x * 256 + threadIdx.x;
    if (i < GK * GK) {
        wq[i] = to_tf32(Wq[i]);
        wo[i] = to_tf32(Wo[i]);
    }
}

// ---------------------------------------------------------------------------
// TF32 GEMM (R6 structure): BM=BN=128, BK=32, 256 thr, warp tile 64x32,
// cp.async double buffer, padded stride 36, grid N-fastest for L2 A reuse.
// R11: B is pre-rounded tf32 (no CVT); A CVT only when CVTA (proj1);
// ROUND epilogue emits tf32-rounded outputs (bit-exact early rounding).
// ---------------------------------------------------------------------------
#define ASTR 36
#define TILE_WORDS (128 * ASTR)     // 4608

template<bool CVTA, bool ROUND>
__global__ __launch_bounds__(256, 2)
void gemm_tf32_kernel(const float* __restrict__ A,
                      const uint32_t* __restrict__ Wt,
                      const float* __restrict__ bias,
                      float* __restrict__ C) {
    extern __shared__ float smem[];
    float* As0 = smem;
    float* As1 = smem + TILE_WORDS;
    float* Bs0 = smem + 2 * TILE_WORDS;
    float* Bs1 = smem + 3 * TILE_WORDS;

    const int tid  = threadIdx.x;
    const int warp = tid >> 5, lane = tid & 31;
    const int qd = lane >> 2, qq = lane & 3;
    const int wm = warp >> 2;     // 0..1 -> 64 rows
    const int wn = warp & 3;      // 0..3 -> 32 cols
    const int mBase = blockIdx.y * 128;   // M slow
    const int nBase = blockIdx.x * 128;   // N fast

    const float* Ab = A + (size_t)mBase * GK;
    const uint32_t* Wb = Wt + (size_t)nBase * GK;

    float c[4][4][4];
    #pragma unroll
    for (int i = 0; i < 4; i++)
        #pragma unroll
        for (int j = 0; j < 4; j++)
            #pragma unroll
            for (int r = 0; r < 4; r++) c[i][j][r] = 0.f;

    auto issue = [&](float* Ad, float* Bd, int kc) {
        #pragma unroll
        for (int l = 0; l < 4; l++) {
            int idx = l * 256 + tid;
            int m   = idx >> 3;
            int kq  = idx & 7;
            uint32_t da = (uint32_t)__cvta_generic_to_shared(&Ad[m * ASTR + kq * 4]);
            const float* sa = Ab + (size_t)m * GK + kc * 32 + kq * 4;
            asm volatile("cp.async.cg.shared.global [%0], [%1], 16;\n" :: "r"(da), "l"(sa));
            uint32_t db = (uint32_t)__cvta_generic_to_shared(&Bd[m * ASTR + kq * 4]);
            const uint32_t* sb = Wb + (size_t)m * GK + kc * 32 + kq * 4;
            asm volatile("cp.async.cg.shared.global [%0], [%1], 16;\n" :: "r"(db), "l"(sb));
        }
        asm volatile("cp.async.commit_group;\n");
    };

    issue(As0, Bs0, 0);

    const int aRow = wm * 64 + qd;
    const int bRow = wn * 32 + qd;

    #pragma unroll 1
    for (int kc = 0; kc < 8; kc++) {
        const bool even = !(kc & 1);
        const float* Ac = even ? As0 : As1;
        const float* Bc = even ? Bs0 : Bs1;

        if (kc < 7) {
            issue(even ? As1 : As0, even ? Bs1 : Bs0, kc + 1);
            asm volatile("cp.async.wait_group 1;\n");
        } else {
            asm volatile("cp.async.wait_group 0;\n");
        }
        __syncthreads();

        const uint32_t* Au = reinterpret_cast<const uint32_t*>(Ac);
        const uint32_t* Bu = reinterpret_cast<const uint32_t*>(Bc);
        #pragma unroll
        for (int ks = 0; ks < 4; ks++) {
            uint32_t af[4][4];
            #pragma unroll
            for (int i = 0; i < 4; i++) {
                if (CVTA) {
                    const float* p0 = &Ac[(aRow + i * 16) * ASTR + ks * 8 + qq];
                    af[i][0] = to_tf32(p0[0]);
                    af[i][2] = to_tf32(p0[4]);
                    af[i][1] = to_tf32(p0[8 * ASTR]);
                    af[i][3] = to_tf32(p0[8 * ASTR + 4]);
                } else {
                    const uint32_t* p0 = &Au[(aRow + i * 16) * ASTR + ks * 8 + qq];
                    af[i][0] = p0[0];
                    af[i][2] = p0[4];
                    af[i][1] = p0[8 * ASTR];
                    af[i][3] = p0[8 * ASTR + 4];
                }
            }
            uint32_t bf[4][2];
            #pragma unroll
            for (int j = 0; j < 4; j++) {
                const uint32_t* pb = &Bu[(bRow + j * 8) * ASTR + ks * 8 + qq];
                bf[j][0] = pb[0];
                bf[j][1] = pb[4];
            }
            #pragma unroll
            for (int i = 0; i < 4; i++)
                #pragma unroll
                for (int j = 0; j < 4; j++)
                    mma_tf32_r(c[i][j], af[i][0], af[i][1], af[i][2], af[i][3],
                               bf[j][0], bf[j][1]);
        }
        __syncthreads();
    }

    // Epilogue: add bias; ROUND -> emit tf32-rounded bits (consumer-identical)
    #pragma unroll
    for (int j = 0; j < 4; j++) {
        int col = nBase + wn * 32 + j * 8 + (lane & 3) * 2;
        float b0 = bias[col], b1 = bias[col + 1];
        #pragma unroll
        for (int i = 0; i < 4; i++) {
            int row0 = mBase + wm * 64 + i * 16 + (lane >> 2);
            float2 v0, v1;
            if (ROUND) {
                v0 = {__uint_as_float(to_tf32(c[i][j][0] + b0)),
                      __uint_as_float(to_tf32(c[i][j][1] + b1))};
                v1 = {__uint_as_float(to_tf32(c[i][j][2] + b0)),
                      __uint_as_float(to_tf32(c[i][j][3] + b1))};
            } else {
                v0 = {c[i][j][0] + b0, c[i][j][1] + b1};
                v1 = {c[i][j][2] + b0, c[i][j][3] + b1};
            }
            *reinterpret_cast<float2*>(C + (size_t)row0 * GK + col) = v0;
            *reinterpret_cast<float2*>(C + (size_t)(row0 + 8) * GK + col) = v1;
        }
    }
}

// ---------------------------------------------------------------------------
// Tensor-core attention (R8 trimmed): one block per (b,g,r,h).
// R11: q arrives tf32-rounded -> stage loads raw; epilogue rounds output
// to tf32 so proj2 can skip its A CVTs. Bit-identical to the R6 chain.
// ---------------------------------------------------------------------------
__global__ __launch_bounds__(128)
void attn_mma_kernel(const float* __restrict__ q, float* __restrict__ out) {
    __shared__ uint32_t Xs[64][68];
    __shared__ uint32_t Xt[64][68];

    int idx = blockIdx.x;
    int h  = idx & 3;
    int r  = (idx >> 2) % RATE;
    int gg = (idx / (RATE * HEADS)) % NSEG;
    int b  = idx / (RATE * HEADS * NSEG);

    const size_t rowBase = ((size_t)b * NTOK + (size_t)gg * (WIN * RATE) + r);
    const uint32_t* base = reinterpret_cast<const uint32_t*>(q + rowBase * DMODEL + h * DH);
    float* obase = out + rowBase * DMODEL + h * DH;

    const int tid  = threadIdx.x;
    const int warp = tid >> 5, lane = tid & 31;
    const int qd = lane >> 2, qq = lane & 3;

    for (int t = tid; t < 15 * 68; t += 128) {
        int rr = t / 68;
        Xs[49 + rr][t - rr * 68] = 0;
    }
    for (int t = tid; t < 64 * 15; t += 128) {
        int d = t / 15;
        Xt[d][49 + (t - d * 15)] = 0;
    }

    // Stage: q values are already tf32-rounded bits; load raw.
    for (int t = tid; t < WIN * 16; t += 128) {
        int row = t >> 4, c4 = t & 15;
        uint4 v = *reinterpret_cast<const uint4*>(
            base + (size_t)row * (RATE * DMODEL) + c4 * 4);
        *reinterpret_cast<uint4*>(&Xs[row][c4 * 4]) = v;
        Xt[c4 * 4 + 0][row] = v.x;
        Xt[c4 * 4 + 1][row] = v.y;
        Xt[c4 * 4 + 2][row] = v.z;
        Xt[c4 * 4 + 3][row] = v.w;
    }
    __syncthreads();

    const int mrow = warp * 16;

    // scores: 7 n-tiles (j < 56)
    float c[7][4];
    #pragma unroll
    for (int nt = 0; nt < 7; nt++)
        #pragma unroll
        for (int k = 0; k < 4; k++) c[nt][k] = 0.f;

    #pragma unroll
    for (int ks = 0; ks < 8; ks++) {
        uint32_t a0 = Xs[mrow + qd][ks * 8 + qq];
        uint32_t a1 = Xs[mrow + qd + 8][ks * 8 + qq];
        uint32_t a2 = Xs[mrow + qd][ks * 8 + qq + 4];
        uint32_t a3 = Xs[mrow + qd + 8][ks * 8 + qq + 4];
        #pragma unroll
        for (int nt = 0; nt < 7; nt++) {
            uint32_t b0 = Xs[nt * 8 + qd][ks * 8 + qq];
            uint32_t b1 = Xs[nt * 8 + qd][ks * 8 + qq + 4];
            mma_tf32_r(c[nt], a0, a1, a2, a3, b0, b1);
        }
    }

    const float scale = 0.125f;
    const float NEG = __int_as_float(0xff800000);
    float m0 = NEG, m1 = NEG;
    #pragma unroll
    for (int nt = 0; nt < 7; nt++)
        #pragma unroll
        for (int par = 0; par < 2; par++) {
            int j = nt * 8 + 2 * qq + par;
            float v0 = (j < WIN) ? c[nt][par] * scale : NEG;
            float v1 = (j < WIN) ? c[nt][par + 2] * scale : NEG;
            c[nt][par] = v0;
            c[nt][par + 2] = v1;
            m0 = fmaxf(m0, v0);
            m1 = fmaxf(m1, v1);
        }
    m0 = fmaxf(m0, __shfl_xor_sync(0xffffffffu, m0, 1));
    m0 = fmaxf(m0, __shfl_xor_sync(0xffffffffu, m0, 2));
    m1 = fmaxf(m1, __shfl_xor_sync(0xffffffffu, m1, 1));
    m1 = fmaxf(m1, __shfl_xor_sync(0xffffffffu, m1, 2));

    float s0 = 0.f, s1 = 0.f;
    #pragma unroll
    for (int nt = 0; nt < 7; nt++)
        #pragma unroll
        for (int par = 0; par < 2; par++) {
            float e0 = __expf(c[nt][par] - m0);
            float e1 = __expf(c[nt][par + 2] - m1);
            c[nt][par] = e0;
            c[nt][par + 2] = e1;
            s0 += e0;
            s1 += e1;
        }
    s0 += __shfl_xor_sync(0xffffffffu, s0, 1);
    s0 += __shfl_xor_sync(0xffffffffu, s0, 2);
    s1 += __shfl_xor_sync(0xffffffffu, s1, 1);
    s1 += __shfl_xor_sync(0xffffffffu, s1, 2);
    float inv0 = 1.f / s0, inv1 = 1.f / s1;

    // PV (7 k-steps)
    float o[8][4];
    #pragma unroll
    for (int nt = 0; nt < 8; nt++)
        #pragma unroll
        for (int k = 0; k < 4; k++) o[nt][k] = 0.f;

    const int srcA = (lane & ~3) + (qq >> 1);
    const bool odd = (qq & 1);

    #pragma unroll
    for (int ks = 0; ks < 7; ks++) {
        float v0 = __shfl_sync(0xffffffffu, c[ks][0], srcA);
        float v1 = __shfl_sync(0xffffffffu, c[ks][1], srcA);
        float v2 = __shfl_sync(0xffffffffu, c[ks][2], srcA);
        float v3 = __shfl_sync(0xffffffffu, c[ks][3], srcA);
        float w0 = __shfl_sync(0xffffffffu, c[ks][0], srcA + 2);
        float w1 = __shfl_sync(0xffffffffu, c[ks][1], srcA + 2);
        float w2 = __shfl_sync(0xffffffffu, c[ks][2], srcA + 2);
        float w3 = __shfl_sync(0xffffffffu, c[ks][3], srcA + 2);
        uint32_t a0 = to_tf32(odd ? v1 : v0);
        uint32_t a1 = to_tf32(odd ? v3 : v2);
        uint32_t a2 = to_tf32(odd ? w1 : w0);
        uint32_t a3 = to_tf32(odd ? w3 : w2);
        #pragma unroll
        for (int nt = 0; nt < 8; nt++) {
            uint32_t b0 = Xt[nt * 8 + qd][ks * 8 + qq];
            uint32_t b1 = Xt[nt * 8 + qd][ks * 8 + qq + 4];
            mma_tf32_r(o[nt], a0, a1, a2, a3, b0, b1);
        }
    }

    // Epilogue: normalize and ROUND to tf32 bits (proj2 reads raw)
    const int r0 = mrow + qd, r1 = r0 + 8;
    #pragma unroll
    for (int nt = 0; nt < 8; nt++) {
        int col = nt * 8 + 2 * qq;
        if (r0 < WIN) {
            float2 v = {__uint_as_float(to_tf32(o[nt][0] * inv0)),
                        __uint_as_float(to_tf32(o[nt][1] * inv0))};
            *reinterpret_cast<float2*>(obase + (size_t)r0 * (RATE * DMODEL) + col) = v;
        }
        if (r1 < WIN) {
            float2 v = {__uint_as_float(to_tf32(o[nt][2] * inv1)),
                        __uint_as_float(to_tf32(o[nt][3] * inv1))};
            *reinterpret_cast<float2*>(obase + (size_t)r1 * (RATE * DMODEL) + col) = v;
        }
    }
}

// ---------------------------------------------------------------------------
// Launch: prep -> proj1 -> attn -> proj2
// ---------------------------------------------------------------------------
extern "C" void kernel_launch(void* const* d_in, const int* in_sizes, int n_in,
                              void* d_out, int out_size) {
    const float* emb = (const float*)d_in[0];
    const float* Wq  = (const float*)d_in[1];
    const float* bq  = (const float*)d_in[2];
    const float* Wo  = (const float*)d_in[3];
    const float* bo  = (const float*)d_in[4];
    float* outp = (float*)d_out;

    float *qbuf = nullptr, *abuf = nullptr;
    uint32_t *wq_t = nullptr, *wo_t = nullptr;
    cudaGetSymbolAddress((void**)&qbuf, g_q);
    cudaGetSymbolAddress((void**)&abuf, g_att);
    cudaGetSymbolAddress((void**)&wq_t, g_wq_t);
    cudaGetSymbolAddress((void**)&wo_t, g_wo_t);

    const int smemBytes = 4 * TILE_WORDS * 4;   // 73728
    static bool attrSet = false;
    if (!attrSet) {
        cudaFuncSetAttribute(gemm_tf32_kernel<true, true>,
                             cudaFuncAttributeMaxDynamicSharedMemorySize, smemBytes);
        cudaFuncSetAttribute(gemm_tf32_kernel<false, false>,
                             cudaFuncAttributeMaxDynamicSharedMemorySize, smemBytes);
        attrSet = true;
    }

    convert_w_kernel<<<GK * GK / 256, 256>>>(Wq, Wo, wq_t, wo_t);

    dim3 ggrid(DMODEL / 128, MROWS / 128);   // (2, 1225), N fastest
    gemm_tf32_kernel<true, true><<<ggrid, 256, smemBytes>>>(emb, wq_t, bq, qbuf);
    attn_mma_kernel<<<BATCH * NSEG * RATE * HEADS, 128>>>(qbuf, abuf);
    gemm_tf32_kernel<false, false><<<ggrid, 256, smemBytes>>>(abuf, wo_t, bo, outp);
}

// round 13
// speedup vs baseline: 1.5233x; 1.5233x over previous
#include <cuda_runtime.h>
#include <cstddef>
#include <cstdint>

// Problem constants
#define BATCH 32
#define NTOK  4900
#define DMODEL 256
#define HEADS 4
#define DH 64
#define WIN 49
#define RATE 5
#define NSEG 20
#define MROWS (BATCH*NTOK)   // 156800
#define GK 256

__device__ float g_q[(size_t)MROWS * DMODEL];
__device__ float g_att[(size_t)MROWS * DMODEL];

__device__ __forceinline__ uint32_t to_tf32(float x) {
    uint32_t y;
    asm("cvt.rna.tf32.f32 %0, %1;" : "=r"(y) : "f"(x));
    return y;
}

__device__ __forceinline__ void mma_tf32_r(float* c,
                                           uint32_t a0, uint32_t a1, uint32_t a2, uint32_t a3,
                                           uint32_t b0, uint32_t b1) {
    asm volatile(
        "mma.sync.aligned.m16n8k8.row.col.f32.tf32.tf32.f32 "
        "{%0,%1,%2,%3}, {%4,%5,%6,%7}, {%8,%9}, {%0,%1,%2,%3};\n"
        : "+f"(c[0]), "+f"(c[1]), "+f"(c[2]), "+f"(c[3])
        : "r"(a0), "r"(a1), "r"(a2), "r"(a3), "r"(b0), "r"(b1));
}

// ---------------------------------------------------------------------------
// TF32 GEMM — EXACT R6 configuration (measured 155us):
// BM=BN=128, BK=32, 256 thr, warp tile 64x32, cp.async double buffer,
// padded smem stride 36 (conflict-free LDS.32 fragment gather),
// grid (N/128 fast, M/128 slow) so sibling blocks share the A tile via L2.
// ---------------------------------------------------------------------------
#define ASTR 36
#define TILE_WORDS (128 * ASTR)     // 4608

__global__ __launch_bounds__(256, 2)
void gemm_tf32_kernel(const float* __restrict__ A,
                      const float* __restrict__ Wt,
                      const float* __restrict__ bias,
                      float* __restrict__ C) {
    extern __shared__ float smem[];
    float* As0 = smem;
    float* As1 = smem + TILE_WORDS;
    float* Bs0 = smem + 2 * TILE_WORDS;
    float* Bs1 = smem + 3 * TILE_WORDS;

    const int tid  = threadIdx.x;
    const int warp = tid >> 5, lane = tid & 31;
    const int qd = lane >> 2, qq = lane & 3;
    const int wm = warp >> 2;     // 0..1 -> 64 rows
    const int wn = warp & 3;      // 0..3 -> 32 cols
    const int mBase = blockIdx.y * 128;   // M slow
    const int nBase = blockIdx.x * 128;   // N fast

    const float* Ab = A + (size_t)mBase * GK;
    const float* Wb = Wt + (size_t)nBase * GK;

    float c[4][4][4];
    #pragma unroll
    for (int i = 0; i < 4; i++)
        #pragma unroll
        for (int j = 0; j < 4; j++)
            #pragma unroll
            for (int r = 0; r < 4; r++) c[i][j][r] = 0.f;

    auto issue = [&](float* Ad, float* Bd, int kc) {
        #pragma unroll
        for (int l = 0; l < 4; l++) {
            int idx = l * 256 + tid;
            int m   = idx >> 3;
            int kq  = idx & 7;
            uint32_t da = (uint32_t)__cvta_generic_to_shared(&Ad[m * ASTR + kq * 4]);
            const float* sa = Ab + (size_t)m * GK + kc * 32 + kq * 4;
            asm volatile("cp.async.cg.shared.global [%0], [%1], 16;\n" :: "r"(da), "l"(sa));
            uint32_t db = (uint32_t)__cvta_generic_to_shared(&Bd[m * ASTR + kq * 4]);
            const float* sb = Wb + (size_t)m * GK + kc * 32 + kq * 4;
            asm volatile("cp.async.cg.shared.global [%0], [%1], 16;\n" :: "r"(db), "l"(sb));
        }
        asm volatile("cp.async.commit_group;\n");
    };

    issue(As0, Bs0, 0);

    const int aRow = wm * 64 + qd;
    const int bRow = wn * 32 + qd;

    #pragma unroll 1
    for (int kc = 0; kc < 8; kc++) {
        const bool even = !(kc & 1);
        const float* Ac = even ? As0 : As1;
        const float* Bc = even ? Bs0 : Bs1;

        if (kc < 7) {
            issue(even ? As1 : As0, even ? Bs1 : Bs0, kc + 1);
            asm volatile("cp.async.wait_group 1;\n");
        } else {
            asm volatile("cp.async.wait_group 0;\n");
        }
        __syncthreads();

        #pragma unroll
        for (int ks = 0; ks < 4; ks++) {
            uint32_t af[4][4];
            #pragma unroll
            for (int i = 0; i < 4; i++) {
                const float* p0 = &Ac[(aRow + i * 16) * ASTR + ks * 8 + qq];
                af[i][0] = to_tf32(p0[0]);
                af[i][2] = to_tf32(p0[4]);
                af[i][1] = to_tf32(p0[8 * ASTR]);
                af[i][3] = to_tf32(p0[8 * ASTR + 4]);
            }
            uint32_t bf[4][2];
            #pragma unroll
            for (int j = 0; j < 4; j++) {
                const float* pb = &Bc[(bRow + j * 8) * ASTR + ks * 8 + qq];
                bf[j][0] = to_tf32(pb[0]);
                bf[j][1] = to_tf32(pb[4]);
            }
            #pragma unroll
            for (int i = 0; i < 4; i++)
                #pragma unroll
                for (int j = 0; j < 4; j++)
                    mma_tf32_r(c[i][j], af[i][0], af[i][1], af[i][2], af[i][3],
                               bf[j][0], bf[j][1]);
        }
        __syncthreads();
    }

    // Epilogue: add bias, write fp32
    #pragma unroll
    for (int j = 0; j < 4; j++) {
        int col = nBase + wn * 32 + j * 8 + (lane & 3) * 2;
        float b0 = bias[col], b1 = bias[col + 1];
        #pragma unroll
        for (int i = 0; i < 4; i++) {
            int row0 = mBase + wm * 64 + i * 16 + (lane >> 2);
            float2 v0 = {c[i][j][0] + b0, c[i][j][1] + b1};
            float2 v1 = {c[i][j][2] + b0, c[i][j][3] + b1};
            *reinterpret_cast<float2*>(C + (size_t)row0 * GK + col) = v0;
            *reinterpret_cast<float2*>(C + (size_t)(row0 + 8) * GK + col) = v1;
        }
    }
}

// ---------------------------------------------------------------------------
// Tensor-core attention: one block per (b,g,r,h), 128 threads (4 warps).
// Trims vs R6: scores 7 n-tiles (j<56), PV 7 k-steps (P==0 for j>=49),
// zero-fill limited to the ranges actually read.
// ---------------------------------------------------------------------------
__global__ __launch_bounds__(128)
void attn_mma_kernel(const float* __restrict__ q, float* __restrict__ out) {
    __shared__ uint32_t Xs[64][68];
    __shared__ uint32_t Xt[64][68];

    int idx = blockIdx.x;
    int h  = idx & 3;
    int r  = (idx >> 2) % RATE;
    int gg = (idx / (RATE * HEADS)) % NSEG;
    int b  = idx / (RATE * HEADS * NSEG);

    const size_t rowBase = ((size_t)b * NTOK + (size_t)gg * (WIN * RATE) + r);
    const float* base = q + rowBase * DMODEL + h * DH;
    float* obase = out + rowBase * DMODEL + h * DH;

    const int tid  = threadIdx.x;
    const int warp = tid >> 5, lane = tid & 31;
    const int qd = lane >> 2, qq = lane & 3;

    // Zero pads: Xs rows 49..63 (A-frags of the pad m-rows read them;
    // B-frags read rows <56). Xt cols 49..55 only (PV k-steps < 7 -> j<56).
    for (int t = tid; t < 15 * 68; t += 128) {
        int rr = t / 68;
        Xs[49 + rr][t - rr * 68] = 0;
    }
    for (int t = tid; t < 64 * 7; t += 128) {
        int d = t / 7;
        Xt[d][49 + (t - d * 7)] = 0;
    }

    // Stage 49x64 tile as tf32 into Xs (rows) and Xt (transposed)
    for (int t = tid; t < WIN * 16; t += 128) {
        int row = t >> 4, c4 = t & 15;
        float4 v = *reinterpret_cast<const float4*>(
            base + (size_t)row * (RATE * DMODEL) + c4 * 4);
        uint32_t u0 = to_tf32(v.x), u1 = to_tf32(v.y);
        uint32_t u2 = to_tf32(v.z), u3 = to_tf32(v.w);
        *reinterpret_cast<uint4*>(&Xs[row][c4 * 4]) = make_uint4(u0, u1, u2, u3);
        Xt[c4 * 4 + 0][row] = u0;
        Xt[c4 * 4 + 1][row] = u1;
        Xt[c4 * 4 + 2][row] = u2;
        Xt[c4 * 4 + 3][row] = u3;
    }
    __syncthreads();

    const int mrow = warp * 16;

    // ---- scores = X X^T : 7 n-tiles (j < 56) ----
    float c[7][4];
    #pragma unroll
    for (int nt = 0; nt < 7; nt++)
        #pragma unroll
        for (int k = 0; k < 4; k++) c[nt][k] = 0.f;

    #pragma unroll
    for (int ks = 0; ks < 8; ks++) {
        uint32_t a0 = Xs[mrow + qd][ks * 8 + qq];
        uint32_t a1 = Xs[mrow + qd + 8][ks * 8 + qq];
        uint32_t a2 = Xs[mrow + qd][ks * 8 + qq + 4];
        uint32_t a3 = Xs[mrow + qd + 8][ks * 8 + qq + 4];
        #pragma unroll
        for (int nt = 0; nt < 7; nt++) {
            uint32_t b0 = Xs[nt * 8 + qd][ks * 8 + qq];
            uint32_t b1 = Xs[nt * 8 + qd][ks * 8 + qq + 4];
            mma_tf32_r(c[nt], a0, a1, a2, a3, b0, b1);
        }
    }

    // ---- mask + softmax in fragments ----
    const float scale = 0.125f;
    const float NEG = __int_as_float(0xff800000);
    float m0 = NEG, m1 = NEG;
    #pragma unroll
    for (int nt = 0; nt < 7; nt++)
        #pragma unroll
        for (int par = 0; par < 2; par++) {
            int j = nt * 8 + 2 * qq + par;
            float v0 = (j < WIN) ? c[nt][par] * scale : NEG;
            float v1 = (j < WIN) ? c[nt][par + 2] * scale : NEG;
            c[nt][par] = v0;
            c[nt][par + 2] = v1;
            m0 = fmaxf(m0, v0);
            m1 = fmaxf(m1, v1);
        }
    m0 = fmaxf(m0, __shfl_xor_sync(0xffffffffu, m0, 1));
    m0 = fmaxf(m0, __shfl_xor_sync(0xffffffffu, m0, 2));
    m1 = fmaxf(m1, __shfl_xor_sync(0xffffffffu, m1, 1));
    m1 = fmaxf(m1, __shfl_xor_sync(0xffffffffu, m1, 2));

    float s0 = 0.f, s1 = 0.f;
    #pragma unroll
    for (int nt = 0; nt < 7; nt++)
        #pragma unroll
        for (int par = 0; par < 2; par++) {
            float e0 = __expf(c[nt][par] - m0);
            float e1 = __expf(c[nt][par + 2] - m1);
            c[nt][par] = e0;
            c[nt][par + 2] = e1;
            s0 += e0;
            s1 += e1;
        }
    s0 += __shfl_xor_sync(0xffffffffu, s0, 1);
    s0 += __shfl_xor_sync(0xffffffffu, s0, 2);
    s1 += __shfl_xor_sync(0xffffffffu, s1, 1);
    s1 += __shfl_xor_sync(0xffffffffu, s1, 2);
    float inv0 = 1.f / s0, inv1 = 1.f / s1;

    // ---- PV: 7 k-steps (j < 56; P exactly 0 for 49<=j<56) ----
    float o[8][4];
    #pragma unroll
    for (int nt = 0; nt < 8; nt++)
        #pragma unroll
        for (int k = 0; k < 4; k++) o[nt][k] = 0.f;

    const int srcA = (lane & ~3) + (qq >> 1);
    const bool odd = (qq & 1);

    #pragma unroll
    for (int ks = 0; ks < 7; ks++) {
        float v0 = __shfl_sync(0xffffffffu, c[ks][0], srcA);
        float v1 = __shfl_sync(0xffffffffu, c[ks][1], srcA);
        float v2 = __shfl_sync(0xffffffffu, c[ks][2], srcA);
        float v3 = __shfl_sync(0xffffffffu, c[ks][3], srcA);
        float w0 = __shfl_sync(0xffffffffu, c[ks][0], srcA + 2);
        float w1 = __shfl_sync(0xffffffffu, c[ks][1], srcA + 2);
        float w2 = __shfl_sync(0xffffffffu, c[ks][2], srcA + 2);
        float w3 = __shfl_sync(0xffffffffu, c[ks][3], srcA + 2);
        uint32_t a0 = to_tf32(odd ? v1 : v0);
        uint32_t a1 = to_tf32(odd ? v3 : v2);
        uint32_t a2 = to_tf32(odd ? w1 : w0);
        uint32_t a3 = to_tf32(odd ? w3 : w2);
        #pragma unroll
        for (int nt = 0; nt < 8; nt++) {
            uint32_t b0 = Xt[nt * 8 + qd][ks * 8 + qq];
            uint32_t b1 = Xt[nt * 8 + qd][ks * 8 + qq + 4];
            mma_tf32_r(o[nt], a0, a1, a2, a3, b0, b1);
        }
    }

    const int r0 = mrow + qd, r1 = r0 + 8;
    #pragma unroll
    for (int nt = 0; nt < 8; nt++) {
        int col = nt * 8 + 2 * qq;
        if (r0 < WIN) {
            float2 v = {o[nt][0] * inv0, o[nt][1] * inv0};
            *reinterpret_cast<float2*>(obase + (size_t)r0 * (RATE * DMODEL) + col) = v;
        }
        if (r1 < WIN) {
            float2 v = {o[nt][2] * inv1, o[nt][3] * inv1};
            *reinterpret_cast<float2*>(obase + (size_t)r1 * (RATE * DMODEL) + col) = v;
        }
    }
}

// ---------------------------------------------------------------------------
// Launch: proj1 -> attention -> proj2 (R6 structure)
// ---------------------------------------------------------------------------
extern "C" void kernel_launch(void* const* d_in, const int* in_sizes, int n_in,
                              void* d_out, int out_size) {
    const float* emb = (const float*)d_in[0];
    const float* Wq  = (const float*)d_in[1];
    const float* bq  = (const float*)d_in[2];
    const float* Wo  = (const float*)d_in[3];
    const float* bo  = (const float*)d_in[4];
    float* outp = (float*)d_out;

    float *qbuf = nullptr, *abuf = nullptr;
    cudaGetSymbolAddress((void**)&qbuf, g_q);
    cudaGetSymbolAddress((void**)&abuf, g_att);

    const int smemBytes = 4 * TILE_WORDS * 4;   // 73728
    static bool attrSet = false;
    if (!attrSet) {
        cudaFuncSetAttribute(gemm_tf32_kernel,
                             cudaFuncAttributeMaxDynamicSharedMemorySize, smemBytes);
        attrSet = true;
    }

    dim3 ggrid(DMODEL / 128, MROWS / 128);   // (2, 1225), N fastest
    gemm_tf32_kernel<<<ggrid, 256, smemBytes>>>(emb, Wq, bq, qbuf);
    attn_mma_kernel<<<BATCH * NSEG * RATE * HEADS, 128>>>(qbuf, abuf);
    gemm_tf32_kernel<<<ggrid, 256, smemBytes>>>(abuf, Wo, bo, outp);
}

// round 14
// speedup vs baseline: 1.6054x; 1.0539x over previous
#include <cuda_runtime.h>
#include <cstddef>
#include <cstdint>

// Problem constants
#define BATCH 32
#define NTOK  4900
#define DMODEL 256
#define HEADS 4
#define DH 64
#define WIN 49
#define RATE 5
#define NSEG 20
#define MROWS (BATCH*NTOK)   // 156800
#define GK 256

__device__ float g_q[(size_t)MROWS * DMODEL];
__device__ float g_att[(size_t)MROWS * DMODEL];

__device__ __forceinline__ uint32_t to_tf32(float x) {
    uint32_t y;
    asm("cvt.rna.tf32.f32 %0, %1;" : "=r"(y) : "f"(x));
    return y;
}

__device__ __forceinline__ void mma_tf32_r(float* c,
                                           uint32_t a0, uint32_t a1, uint32_t a2, uint32_t a3,
                                           uint32_t b0, uint32_t b1) {
    asm volatile(
        "mma.sync.aligned.m16n8k8.row.col.f32.tf32.tf32.f32 "
        "{%0,%1,%2,%3}, {%4,%5,%6,%7}, {%8,%9}, {%0,%1,%2,%3};\n"
        : "+f"(c[0]), "+f"(c[1]), "+f"(c[2]), "+f"(c[3])
        : "r"(a0), "r"(a1), "r"(a2), "r"(a3), "r"(b0), "r"(b1));
}

// ---------------------------------------------------------------------------
// TF32 GEMM — EXACT R6/R13 configuration (measured 153us). DO NOT TOUCH.
// ---------------------------------------------------------------------------
#define ASTR 36
#define TILE_WORDS (128 * ASTR)     // 4608

__global__ __launch_bounds__(256, 2)
void gemm_tf32_kernel(const float* __restrict__ A,
                      const float* __restrict__ Wt,
                      const float* __restrict__ bias,
                      float* __restrict__ C) {
    extern __shared__ float smem[];
    float* As0 = smem;
    float* As1 = smem + TILE_WORDS;
    float* Bs0 = smem + 2 * TILE_WORDS;
    float* Bs1 = smem + 3 * TILE_WORDS;

    const int tid  = threadIdx.x;
    const int warp = tid >> 5, lane = tid & 31;
    const int qd = lane >> 2, qq = lane & 3;
    const int wm = warp >> 2;     // 0..1 -> 64 rows
    const int wn = warp & 3;      // 0..3 -> 32 cols
    const int mBase = blockIdx.y * 128;   // M slow
    const int nBase = blockIdx.x * 128;   // N fast

    const float* Ab = A + (size_t)mBase * GK;
    const float* Wb = Wt + (size_t)nBase * GK;

    float c[4][4][4];
    #pragma unroll
    for (int i = 0; i < 4; i++)
        #pragma unroll
        for (int j = 0; j < 4; j++)
            #pragma unroll
            for (int r = 0; r < 4; r++) c[i][j][r] = 0.f;

    auto issue = [&](float* Ad, float* Bd, int kc) {
        #pragma unroll
        for (int l = 0; l < 4; l++) {
            int idx = l * 256 + tid;
            int m   = idx >> 3;
            int kq  = idx & 7;
            uint32_t da = (uint32_t)__cvta_generic_to_shared(&Ad[m * ASTR + kq * 4]);
            const float* sa = Ab + (size_t)m * GK + kc * 32 + kq * 4;
            asm volatile("cp.async.cg.shared.global [%0], [%1], 16;\n" :: "r"(da), "l"(sa));
            uint32_t db = (uint32_t)__cvta_generic_to_shared(&Bd[m * ASTR + kq * 4]);
            const float* sb = Wb + (size_t)m * GK + kc * 32 + kq * 4;
            asm volatile("cp.async.cg.shared.global [%0], [%1], 16;\n" :: "r"(db), "l"(sb));
        }
        asm volatile("cp.async.commit_group;\n");
    };

    issue(As0, Bs0, 0);

    const int aRow = wm * 64 + qd;
    const int bRow = wn * 32 + qd;

    #pragma unroll 1
    for (int kc = 0; kc < 8; kc++) {
        const bool even = !(kc & 1);
        const float* Ac = even ? As0 : As1;
        const float* Bc = even ? Bs0 : Bs1;

        if (kc < 7) {
            issue(even ? As1 : As0, even ? Bs1 : Bs0, kc + 1);
            asm volatile("cp.async.wait_group 1;\n");
        } else {
            asm volatile("cp.async.wait_group 0;\n");
        }
        __syncthreads();

        #pragma unroll
        for (int ks = 0; ks < 4; ks++) {
            uint32_t af[4][4];
            #pragma unroll
            for (int i = 0; i < 4; i++) {
                const float* p0 = &Ac[(aRow + i * 16) * ASTR + ks * 8 + qq];
                af[i][0] = to_tf32(p0[0]);
                af[i][2] = to_tf32(p0[4]);
                af[i][1] = to_tf32(p0[8 * ASTR]);
                af[i][3] = to_tf32(p0[8 * ASTR + 4]);
            }
            uint32_t bf[4][2];
            #pragma unroll
            for (int j = 0; j < 4; j++) {
                const float* pb = &Bc[(bRow + j * 8) * ASTR + ks * 8 + qq];
                bf[j][0] = to_tf32(pb[0]);
                bf[j][1] = to_tf32(pb[4]);
            }
            #pragma unroll
            for (int i = 0; i < 4; i++)
                #pragma unroll
                for (int j = 0; j < 4; j++)
                    mma_tf32_r(c[i][j], af[i][0], af[i][1], af[i][2], af[i][3],
                               bf[j][0], bf[j][1]);
        }
        __syncthreads();
    }

    // Epilogue: add bias, write fp32
    #pragma unroll
    for (int j = 0; j < 4; j++) {
        int col = nBase + wn * 32 + j * 8 + (lane & 3) * 2;
        float b0 = bias[col], b1 = bias[col + 1];
        #pragma unroll
        for (int i = 0; i < 4; i++) {
            int row0 = mBase + wm * 64 + i * 16 + (lane >> 2);
            float2 v0 = {c[i][j][0] + b0, c[i][j][1] + b1};
            float2 v1 = {c[i][j][2] + b0, c[i][j][3] + b1};
            *reinterpret_cast<float2*>(C + (size_t)row0 * GK + col) = v0;
            *reinterpret_cast<float2*>(C + (size_t)(row0 + 8) * GK + col) = v1;
        }
    }
}

// ---------------------------------------------------------------------------
// Tensor-core attention: one block per (b,g,r,h), 128 threads (4 warps).
// R14: Xt eliminated — PV B-fragments read directly from Xs (2-way
// conflicted LDS instead of an 8-way-conflicted transpose scatter).
// smem halves to 17.4KB. Scores 7 n-tiles, PV 7 k-steps (as R13).
// ---------------------------------------------------------------------------
__global__ __launch_bounds__(128)
void attn_mma_kernel(const float* __restrict__ q, float* __restrict__ out) {
    __shared__ uint32_t Xs[64][68];

    int idx = blockIdx.x;
    int h  = idx & 3;
    int r  = (idx >> 2) % RATE;
    int gg = (idx / (RATE * HEADS)) % NSEG;
    int b  = idx / (RATE * HEADS * NSEG);

    const size_t rowBase = ((size_t)b * NTOK + (size_t)gg * (WIN * RATE) + r);
    const float* base = q + rowBase * DMODEL + h * DH;
    float* obase = out + rowBase * DMODEL + h * DH;

    const int tid  = threadIdx.x;
    const int warp = tid >> 5, lane = tid & 31;
    const int qd = lane >> 2, qq = lane & 3;

    // Zero pad rows 49..55 (read as scores-B rows and PV-B tokens; rows
    // 56..63 are read only as A-frags of discarded output rows).
    for (int t = tid; t < 7 * 68; t += 128) {
        int rr = t / 68;
        Xs[49 + rr][t - rr * 68] = 0;
    }

    // Stage 49x64 tile as tf32 into Xs
    for (int t = tid; t < WIN * 16; t += 128) {
        int row = t >> 4, c4 = t & 15;
        float4 v = *reinterpret_cast<const float4*>(
            base + (size_t)row * (RATE * DMODEL) + c4 * 4);
        *reinterpret_cast<uint4*>(&Xs[row][c4 * 4]) =
            make_uint4(to_tf32(v.x), to_tf32(v.y), to_tf32(v.z), to_tf32(v.w));
    }
    __syncthreads();

    const int mrow = warp * 16;

    // ---- scores = X X^T : 7 n-tiles (j < 56) ----
    float c[7][4];
    #pragma unroll
    for (int nt = 0; nt < 7; nt++)
        #pragma unroll
        for (int k = 0; k < 4; k++) c[nt][k] = 0.f;

    #pragma unroll
    for (int ks = 0; ks < 8; ks++) {
        uint32_t a0 = Xs[mrow + qd][ks * 8 + qq];
        uint32_t a1 = Xs[mrow + qd + 8][ks * 8 + qq];
        uint32_t a2 = Xs[mrow + qd][ks * 8 + qq + 4];
        uint32_t a3 = Xs[mrow + qd + 8][ks * 8 + qq + 4];
        #pragma unroll
        for (int nt = 0; nt < 7; nt++) {
            uint32_t b0 = Xs[nt * 8 + qd][ks * 8 + qq];
            uint32_t b1 = Xs[nt * 8 + qd][ks * 8 + qq + 4];
            mma_tf32_r(c[nt], a0, a1, a2, a3, b0, b1);
        }
    }

    // ---- mask + softmax in fragments ----
    const float scale = 0.125f;
    const float NEG = __int_as_float(0xff800000);
    float m0 = NEG, m1 = NEG;
    #pragma unroll
    for (int nt = 0; nt < 7; nt++)
        #pragma unroll
        for (int par = 0; par < 2; par++) {
            int j = nt * 8 + 2 * qq + par;
            float v0 = (j < WIN) ? c[nt][par] * scale : NEG;
            float v1 = (j < WIN) ? c[nt][par + 2] * scale : NEG;
            c[nt][par] = v0;
            c[nt][par + 2] = v1;
            m0 = fmaxf(m0, v0);
            m1 = fmaxf(m1, v1);
        }
    m0 = fmaxf(m0, __shfl_xor_sync(0xffffffffu, m0, 1));
    m0 = fmaxf(m0, __shfl_xor_sync(0xffffffffu, m0, 2));
    m1 = fmaxf(m1, __shfl_xor_sync(0xffffffffu, m1, 1));
    m1 = fmaxf(m1, __shfl_xor_sync(0xffffffffu, m1, 2));

    float s0 = 0.f, s1 = 0.f;
    #pragma unroll
    for (int nt = 0; nt < 7; nt++)
        #pragma unroll
        for (int par = 0; par < 2; par++) {
            float e0 = __expf(c[nt][par] - m0);
            float e1 = __expf(c[nt][par + 2] - m1);
            c[nt][par] = e0;
            c[nt][par + 2] = e1;
            s0 += e0;
            s1 += e1;
        }
    s0 += __shfl_xor_sync(0xffffffffu, s0, 1);
    s0 += __shfl_xor_sync(0xffffffffu, s0, 2);
    s1 += __shfl_xor_sync(0xffffffffu, s1, 1);
    s1 += __shfl_xor_sync(0xffffffffu, s1, 2);
    float inv0 = 1.f / s0, inv1 = 1.f / s1;

    // ---- PV: 7 k-steps; B[n][k] = X[k][n] read directly from Xs ----
    float o[8][4];
    #pragma unroll
    for (int nt = 0; nt < 8; nt++)
        #pragma unroll
        for (int k = 0; k < 4; k++) o[nt][k] = 0.f;

    const int srcA = (lane & ~3) + (qq >> 1);
    const bool odd = (qq & 1);

    #pragma unroll
    for (int ks = 0; ks < 7; ks++) {
        float v0 = __shfl_sync(0xffffffffu, c[ks][0], srcA);
        float v1 = __shfl_sync(0xffffffffu, c[ks][1], srcA);
        float v2 = __shfl_sync(0xffffffffu, c[ks][2], srcA);
        float v3 = __shfl_sync(0xffffffffu, c[ks][3], srcA);
        float w0 = __shfl_sync(0xffffffffu, c[ks][0], srcA + 2);
        float w1 = __shfl_sync(0xffffffffu, c[ks][1], srcA + 2);
        float w2 = __shfl_sync(0xffffffffu, c[ks][2], srcA + 2);
        float w3 = __shfl_sync(0xffffffffu, c[ks][3], srcA + 2);
        uint32_t a0 = to_tf32(odd ? v1 : v0);
        uint32_t a1 = to_tf32(odd ? v3 : v2);
        uint32_t a2 = to_tf32(odd ? w1 : w0);
        uint32_t a3 = to_tf32(odd ? w3 : w2);
        #pragma unroll
        for (int nt = 0; nt < 8; nt++) {
            uint32_t b0 = Xs[ks * 8 + qq][nt * 8 + qd];
            uint32_t b1 = Xs[ks * 8 + qq + 4][nt * 8 + qd];
            mma_tf32_r(o[nt], a0, a1, a2, a3, b0, b1);
        }
    }

    const int r0 = mrow + qd, r1 = r0 + 8;
    #pragma unroll
    for (int nt = 0; nt < 8; nt++) {
        int col = nt * 8 + 2 * qq;
        if (r0 < WIN) {
            float2 v = {o[nt][0] * inv0, o[nt][1] * inv0};
            *reinterpret_cast<float2*>(obase + (size_t)r0 * (RATE * DMODEL) + col) = v;
        }
        if (r1 < WIN) {
            float2 v = {o[nt][2] * inv1, o[nt][3] * inv1};
            *reinterpret_cast<float2*>(obase + (size_t)r1 * (RATE * DMODEL) + col) = v;
        }
    }
}

// ---------------------------------------------------------------------------
// Launch: proj1 -> attention -> proj2
// ---------------------------------------------------------------------------
extern "C" void kernel_launch(void* const* d_in, const int* in_sizes, int n_in,
                              void* d_out, int out_size) {
    const float* emb = (const float*)d_in[0];
    const float* Wq  = (const float*)d_in[1];
    const float* bq  = (const float*)d_in[2];
    const float* Wo  = (const float*)d_in[3];
    const float* bo  = (const float*)d_in[4];
    float* outp = (float*)d_out;

    float *qbuf = nullptr, *abuf = nullptr;
    cudaGetSymbolAddress((void**)&qbuf, g_q);
    cudaGetSymbolAddress((void**)&abuf, g_att);

    const int smemBytes = 4 * TILE_WORDS * 4;   // 73728
    static bool attrSet = false;
    if (!attrSet) {
        cudaFuncSetAttribute(gemm_tf32_kernel,
                             cudaFuncAttributeMaxDynamicSharedMemorySize, smemBytes);
        attrSet = true;
    }

    dim3 ggrid(DMODEL / 128, MROWS / 128);   // (2, 1225), N fastest
    gemm_tf32_kernel<<<ggrid, 256, smemBytes>>>(emb, Wq, bq, qbuf);
    attn_mma_kernel<<<BATCH * NSEG * RATE * HEADS, 128>>>(qbuf, abuf);
    gemm_tf32_kernel<<<ggrid, 256, smemBytes>>>(abuf, Wo, bo, outp);
}

// round 15
// speedup vs baseline: 1.6369x; 1.0196x over previous
#include <cuda_runtime.h>
#include <cstddef>
#include <cstdint>

// Problem constants
#define BATCH 32
#define NTOK  4900
#define DMODEL 256
#define HEADS 4
#define DH 64
#define WIN 49
#define RATE 5
#define NSEG 20
#define MROWS (BATCH*NTOK)   // 156800
#define GK 256

// Chunked pipeline: 8 chunks x 4 batches
#define NCHUNK 8
#define BATCH_PER_CHUNK 4
#define ROWS_PER_CHUNK (BATCH_PER_CHUNK * NTOK)   // 19600
#define TILES_PER_CHUNK ((ROWS_PER_CHUNK + 127) / 128)  // 154

__device__ float g_q[(size_t)MROWS * DMODEL];
__device__ float g_att[(size_t)MROWS * DMODEL];

__device__ __forceinline__ uint32_t to_tf32(float x) {
    uint32_t y;
    asm("cvt.rna.tf32.f32 %0, %1;" : "=r"(y) : "f"(x));
    return y;
}

__device__ __forceinline__ void mma_tf32_r(float* c,
                                           uint32_t a0, uint32_t a1, uint32_t a2, uint32_t a3,
                                           uint32_t b0, uint32_t b1) {
    asm volatile(
        "mma.sync.aligned.m16n8k8.row.col.f32.tf32.tf32.f32 "
        "{%0,%1,%2,%3}, {%4,%5,%6,%7}, {%8,%9}, {%0,%1,%2,%3};\n"
        : "+f"(c[0]), "+f"(c[1]), "+f"(c[2]), "+f"(c[3])
        : "r"(a0), "r"(a1), "r"(a2), "r"(a3), "r"(b0), "r"(b1));
}

// ---------------------------------------------------------------------------
// TF32 GEMM — R6/R13 mainloop (153us config), now over rows [mStart, mEnd):
// loads clamped to mEnd-1 (discarded outputs), stores guarded.
// ---------------------------------------------------------------------------
#define ASTR 36
#define TILE_WORDS (128 * ASTR)     // 4608

__global__ __launch_bounds__(256, 2)
void gemm_tf32_kernel(const float* __restrict__ A,
                      const float* __restrict__ Wt,
                      const float* __restrict__ bias,
                      float* __restrict__ C,
                      int mStart, int mEnd) {
    extern __shared__ float smem[];
    float* As0 = smem;
    float* As1 = smem + TILE_WORDS;
    float* Bs0 = smem + 2 * TILE_WORDS;
    float* Bs1 = smem + 3 * TILE_WORDS;

    const int tid  = threadIdx.x;
    const int warp = tid >> 5, lane = tid & 31;
    const int qd = lane >> 2, qq = lane & 3;
    const int wm = warp >> 2;     // 0..1 -> 64 rows
    const int wn = warp & 3;      // 0..3 -> 32 cols
    const int mBase = mStart + blockIdx.y * 128;
    const int nBase = blockIdx.x * 128;

    const float* Wb = Wt + (size_t)nBase * GK;

    float c[4][4][4];
    #pragma unroll
    for (int i = 0; i < 4; i++)
        #pragma unroll
        for (int j = 0; j < 4; j++)
            #pragma unroll
            for (int r = 0; r < 4; r++) c[i][j][r] = 0.f;

    auto issue = [&](float* Ad, float* Bd, int kc) {
        #pragma unroll
        for (int l = 0; l < 4; l++) {
            int idx = l * 256 + tid;
            int m   = idx >> 3;
            int kq  = idx & 7;
            int gm  = mBase + m;
            gm = (gm < mEnd) ? gm : (mEnd - 1);
            uint32_t da = (uint32_t)__cvta_generic_to_shared(&Ad[m * ASTR + kq * 4]);
            const float* sa = A + (size_t)gm * GK + kc * 32 + kq * 4;
            asm volatile("cp.async.cg.shared.global [%0], [%1], 16;\n" :: "r"(da), "l"(sa));
            uint32_t db = (uint32_t)__cvta_generic_to_shared(&Bd[m * ASTR + kq * 4]);
            const float* sb = Wb + (size_t)m * GK + kc * 32 + kq * 4;
            asm volatile("cp.async.cg.shared.global [%0], [%1], 16;\n" :: "r"(db), "l"(sb));
        }
        asm volatile("cp.async.commit_group;\n");
    };

    issue(As0, Bs0, 0);

    const int aRow = wm * 64 + qd;
    const int bRow = wn * 32 + qd;

    #pragma unroll 1
    for (int kc = 0; kc < 8; kc++) {
        const bool even = !(kc & 1);
        const float* Ac = even ? As0 : As1;
        const float* Bc = even ? Bs0 : Bs1;

        if (kc < 7) {
            issue(even ? As1 : As0, even ? Bs1 : Bs0, kc + 1);
            asm volatile("cp.async.wait_group 1;\n");
        } else {
            asm volatile("cp.async.wait_group 0;\n");
        }
        __syncthreads();

        #pragma unroll
        for (int ks = 0; ks < 4; ks++) {
            uint32_t af[4][4];
            #pragma unroll
            for (int i = 0; i < 4; i++) {
                const float* p0 = &Ac[(aRow + i * 16) * ASTR + ks * 8 + qq];
                af[i][0] = to_tf32(p0[0]);
                af[i][2] = to_tf32(p0[4]);
                af[i][1] = to_tf32(p0[8 * ASTR]);
                af[i][3] = to_tf32(p0[8 * ASTR + 4]);
            }
            uint32_t bf[4][2];
            #pragma unroll
            for (int j = 0; j < 4; j++) {
                const float* pb = &Bc[(bRow + j * 8) * ASTR + ks * 8 + qq];
                bf[j][0] = to_tf32(pb[0]);
                bf[j][1] = to_tf32(pb[4]);
            }
            #pragma unroll
            for (int i = 0; i < 4; i++)
                #pragma unroll
                for (int j = 0; j < 4; j++)
                    mma_tf32_r(c[i][j], af[i][0], af[i][1], af[i][2], af[i][3],
                               bf[j][0], bf[j][1]);
        }
        __syncthreads();
    }

    // Epilogue: add bias, write fp32 (guarded to [mStart, mEnd))
    #pragma unroll
    for (int j = 0; j < 4; j++) {
        int col = nBase + wn * 32 + j * 8 + (lane & 3) * 2;
        float b0 = bias[col], b1 = bias[col + 1];
        #pragma unroll
        for (int i = 0; i < 4; i++) {
            int row0 = mBase + wm * 64 + i * 16 + (lane >> 2);
            if (row0 < mEnd) {
                float2 v0 = {c[i][j][0] + b0, c[i][j][1] + b1};
                *reinterpret_cast<float2*>(C + (size_t)row0 * GK + col) = v0;
            }
            if (row0 + 8 < mEnd) {
                float2 v1 = {c[i][j][2] + b0, c[i][j][3] + b1};
                *reinterpret_cast<float2*>(C + (size_t)(row0 + 8) * GK + col) = v1;
            }
        }
    }
}

// ---------------------------------------------------------------------------
// Tensor-core attention (R14): one block per (b,g,r,h) within a batch chunk.
// ---------------------------------------------------------------------------
__global__ __launch_bounds__(128)
void attn_mma_kernel(const float* __restrict__ q, float* __restrict__ out,
                     int bOff) {
    __shared__ uint32_t Xs[64][68];

    int idx = blockIdx.x;
    int h  = idx & 3;
    int r  = (idx >> 2) % RATE;
    int gg = (idx / (RATE * HEADS)) % NSEG;
    int b  = bOff + idx / (RATE * HEADS * NSEG);

    const size_t rowBase = ((size_t)b * NTOK + (size_t)gg * (WIN * RATE) + r);
    const float* base = q + rowBase * DMODEL + h * DH;
    float* obase = out + rowBase * DMODEL + h * DH;

    const int tid  = threadIdx.x;
    const int warp = tid >> 5, lane = tid & 31;
    const int qd = lane >> 2, qq = lane & 3;

    for (int t = tid; t < 7 * 68; t += 128) {
        int rr = t / 68;
        Xs[49 + rr][t - rr * 68] = 0;
    }

    for (int t = tid; t < WIN * 16; t += 128) {
        int row = t >> 4, c4 = t & 15;
        float4 v = *reinterpret_cast<const float4*>(
            base + (size_t)row * (RATE * DMODEL) + c4 * 4);
        *reinterpret_cast<uint4*>(&Xs[row][c4 * 4]) =
            make_uint4(to_tf32(v.x), to_tf32(v.y), to_tf32(v.z), to_tf32(v.w));
    }
    __syncthreads();

    const int mrow = warp * 16;

    float c[7][4];
    #pragma unroll
    for (int nt = 0; nt < 7; nt++)
        #pragma unroll
        for (int k = 0; k < 4; k++) c[nt][k] = 0.f;

    #pragma unroll
    for (int ks = 0; ks < 8; ks++) {
        uint32_t a0 = Xs[mrow + qd][ks * 8 + qq];
        uint32_t a1 = Xs[mrow + qd + 8][ks * 8 + qq];
        uint32_t a2 = Xs[mrow + qd][ks * 8 + qq + 4];
        uint32_t a3 = Xs[mrow + qd + 8][ks * 8 + qq + 4];
        #pragma unroll
        for (int nt = 0; nt < 7; nt++) {
            uint32_t b0 = Xs[nt * 8 + qd][ks * 8 + qq];
            uint32_t b1 = Xs[nt * 8 + qd][ks * 8 + qq + 4];
            mma_tf32_r(c[nt], a0, a1, a2, a3, b0, b1);
        }
    }

    const float scale = 0.125f;
    const float NEG = __int_as_float(0xff800000);
    float m0 = NEG, m1 = NEG;
    #pragma unroll
    for (int nt = 0; nt < 7; nt++)
        #pragma unroll
        for (int par = 0; par < 2; par++) {
            int j = nt * 8 + 2 * qq + par;
            float v0 = (j < WIN) ? c[nt][par] * scale : NEG;
            float v1 = (j < WIN) ? c[nt][par + 2] * scale : NEG;
            c[nt][par] = v0;
            c[nt][par + 2] = v1;
            m0 = fmaxf(m0, v0);
            m1 = fmaxf(m1, v1);
        }
    m0 = fmaxf(m0, __shfl_xor_sync(0xffffffffu, m0, 1));
    m0 = fmaxf(m0, __shfl_xor_sync(0xffffffffu, m0, 2));
    m1 = fmaxf(m1, __shfl_xor_sync(0xffffffffu, m1, 1));
    m1 = fmaxf(m1, __shfl_xor_sync(0xffffffffu, m1, 2));

    float s0 = 0.f, s1 = 0.f;
    #pragma unroll
    for (int nt = 0; nt < 7; nt++)
        #pragma unroll
        for (int par = 0; par < 2; par++) {
            float e0 = __expf(c[nt][par] - m0);
            float e1 = __expf(c[nt][par + 2] - m1);
            c[nt][par] = e0;
            c[nt][par + 2] = e1;
            s0 += e0;
            s1 += e1;
        }
    s0 += __shfl_xor_sync(0xffffffffu, s0, 1);
    s0 += __shfl_xor_sync(0xffffffffu, s0, 2);
    s1 += __shfl_xor_sync(0xffffffffu, s1, 1);
    s1 += __shfl_xor_sync(0xffffffffu, s1, 2);
    float inv0 = 1.f / s0, inv1 = 1.f / s1;

    float o[8][4];
    #pragma unroll
    for (int nt = 0; nt < 8; nt++)
        #pragma unroll
        for (int k = 0; k < 4; k++) o[nt][k] = 0.f;

    const int srcA = (lane & ~3) + (qq >> 1);
    const bool odd = (qq & 1);

    #pragma unroll
    for (int ks = 0; ks < 7; ks++) {
        float v0 = __shfl_sync(0xffffffffu, c[ks][0], srcA);
        float v1 = __shfl_sync(0xffffffffu, c[ks][1], srcA);
        float v2 = __shfl_sync(0xffffffffu, c[ks][2], srcA);
        float v3 = __shfl_sync(0xffffffffu, c[ks][3], srcA);
        float w0 = __shfl_sync(0xffffffffu, c[ks][0], srcA + 2);
        float w1 = __shfl_sync(0xffffffffu, c[ks][1], srcA + 2);
        float w2 = __shfl_sync(0xffffffffu, c[ks][2], srcA + 2);
        float w3 = __shfl_sync(0xffffffffu, c[ks][3], srcA + 2);
        uint32_t a0 = to_tf32(odd ? v1 : v0);
        uint32_t a1 = to_tf32(odd ? v3 : v2);
        uint32_t a2 = to_tf32(odd ? w1 : w0);
        uint32_t a3 = to_tf32(odd ? w3 : w2);
        #pragma unroll
        for (int nt = 0; nt < 8; nt++) {
            uint32_t b0 = Xs[ks * 8 + qq][nt * 8 + qd];
            uint32_t b1 = Xs[ks * 8 + qq + 4][nt * 8 + qd];
            mma_tf32_r(o[nt], a0, a1, a2, a3, b0, b1);
        }
    }

    const int r0 = mrow + qd, r1 = r0 + 8;
    #pragma unroll
    for (int nt = 0; nt < 8; nt++) {
        int col = nt * 8 + 2 * qq;
        if (r0 < WIN) {
            float2 v = {o[nt][0] * inv0, o[nt][1] * inv0};
            *reinterpret_cast<float2*>(obase + (size_t)r0 * (RATE * DMODEL) + col) = v;
        }
        if (r1 < WIN) {
            float2 v = {o[nt][2] * inv1, o[nt][3] * inv1};
            *reinterpret_cast<float2*>(obase + (size_t)r1 * (RATE * DMODEL) + col) = v;
        }
    }
}

// ---------------------------------------------------------------------------
// Launch: 8 batch-chunks pipelined across 2 non-blocking streams.
// Fork/join via events on the (captured) default stream.
// ---------------------------------------------------------------------------
extern "C" void kernel_launch(void* const* d_in, const int* in_sizes, int n_in,
                              void* d_out, int out_size) {
    const float* emb = (const float*)d_in[0];
    const float* Wq  = (const float*)d_in[1];
    const float* bq  = (const float*)d_in[2];
    const float* Wo  = (const float*)d_in[3];
    const float* bo  = (const float*)d_in[4];
    float* outp = (float*)d_out;

    float *qbuf = nullptr, *abuf = nullptr;
    cudaGetSymbolAddress((void**)&qbuf, g_q);
    cudaGetSymbolAddress((void**)&abuf, g_att);

    const int smemBytes = 4 * TILE_WORDS * 4;   // 73728
    static cudaStream_t s[2];
    static cudaEvent_t eFork, eJoin0, eJoin1;
    static bool inited = false;
    if (!inited) {
        cudaFuncSetAttribute(gemm_tf32_kernel,
                             cudaFuncAttributeMaxDynamicSharedMemorySize, smemBytes);
        cudaStreamCreateWithFlags(&s[0], cudaStreamNonBlocking);
        cudaStreamCreateWithFlags(&s[1], cudaStreamNonBlocking);
        cudaEventCreateWithFlags(&eFork,  cudaEventDisableTiming);
        cudaEventCreateWithFlags(&eJoin0, cudaEventDisableTiming);
        cudaEventCreateWithFlags(&eJoin1, cudaEventDisableTiming);
        inited = true;
    }

    // Fork from the (captured) default stream
    cudaEventRecord(eFork, 0);
    cudaStreamWaitEvent(s[0], eFork, 0);
    cudaStreamWaitEvent(s[1], eFork, 0);

    dim3 ggrid(DMODEL / 128, TILES_PER_CHUNK);   // (2, 154)
    for (int i = 0; i < NCHUNK; i++) {
        cudaStream_t st = s[i & 1];
        int mStart = i * ROWS_PER_CHUNK;
        int mEnd   = mStart + ROWS_PER_CHUNK;
        gemm_tf32_kernel<<<ggrid, 256, smemBytes, st>>>(emb, Wq, bq, qbuf, mStart, mEnd);
        attn_mma_kernel<<<BATCH_PER_CHUNK * NSEG * RATE * HEADS, 128, 0, st>>>(
            qbuf, abuf, i * BATCH_PER_CHUNK);
        gemm_tf32_kernel<<<ggrid, 256, smemBytes, st>>>(abuf, Wo, bo, outp, mStart, mEnd);
    }

    // Join back to the default stream
    cudaEventRecord(eJoin0, s[0]);
    cudaEventRecord(eJoin1, s[1]);
    cudaStreamWaitEvent(0, eJoin0, 0);
    cudaStreamWaitEvent(0, eJoin1, 0);
}